// round 15
// baseline (speedup 1.0000x reference)
#include <cuda_runtime.h>
#include <cuda_fp16.h>
#include <math.h>
#include <stdint.h>

#define NN   100000
#define EE   1600000
#define ENL  1700000     // edges + self loops
#define FIN  1024
#define F1   128         // H1*C1
#define H1   16
#define C2   19
#define C2P  20
#define NB1  ((NN + 255) / 256)   // 391 scan blocks

// ---------------- scratch (device globals; no allocation allowed) ----------------
__device__ __half   g_h1h  [(size_t)NN * F1];   // h1 in fp16 (halves agg1 gather traffic)
__device__ float    g_asrc1[NN * H1];
__device__ float    g_adst1[NN * H1];
__device__ float    g_h2   [NN * C2P];
__device__ float    g_asrc2[NN];
__device__ float    g_adst2[NN];
// CSR by destination
__device__ int      g_cnt  [NN];
__device__ int      g_row  [NN + 1];
__device__ int      g_wpos [NN];
__device__ int      g_bsum [512];
__device__ int      g_esrc [ENL];
// W1^T in fp16, pre-laid-out in the smem/ldmatrix layout:
// tile kt = [128 n-rows][64 k-cols] fp16, 128B rows, chunk ^= (row&7) swizzle.
__device__ __align__(16) __half g_Bh[16 * 8192];

// ---------------- helpers ----------------
__device__ __forceinline__ float lrelu(float x) { return x >= 0.f ? x : 0.2f * x; }

__device__ __forceinline__ void edge_sd(const int* __restrict__ ei, int e, int& s, int& d) {
    if (e < EE) { s = ei[e]; d = ei[EE + e]; }
    else        { s = e - EE; d = s; }
}

__device__ __forceinline__ void ldsm4(uint4& r, uint32_t addr) {
    asm volatile("ldmatrix.sync.aligned.m8n8.x4.shared.b16 {%0,%1,%2,%3}, [%4];"
                 : "=r"(r.x), "=r"(r.y), "=r"(r.z), "=r"(r.w) : "r"(addr));
}

__device__ __forceinline__ void mma16816(float* d, const uint4& a, uint32_t b0, uint32_t b1) {
    asm volatile(
        "mma.sync.aligned.m16n8k16.row.col.f32.f16.f16.f32 "
        "{%0,%1,%2,%3}, {%4,%5,%6,%7}, {%8,%9}, {%0,%1,%2,%3};"
        : "+f"(d[0]), "+f"(d[1]), "+f"(d[2]), "+f"(d[3])
        : "r"(a.x), "r"(a.y), "r"(a.z), "r"(a.w), "r"(b0), "r"(b1));
}

__device__ __forceinline__ void cpasync16(uint32_t dst, const void* src) {
    asm volatile("cp.async.cg.shared.global [%0], [%1], 16;" :: "r"(dst), "l"(src) : "memory");
}

// ---------------- init: zero histogram only ----------------
__global__ void k_init() {
    int i = blockIdx.x * blockDim.x + threadIdx.x;
    if (i < NN) g_cnt[i] = 0;
}

// ---------------- CSR build ----------------
__global__ void k_hist(const int* __restrict__ ei) {
    int e = blockIdx.x * blockDim.x + threadIdx.x;
    if (e >= ENL) return;
    int s, d; edge_sd(ei, e, s, d);
    atomicAdd(&g_cnt[d], 1);
}

__global__ void k_scan1() {
    __shared__ int ws[8];
    int t = threadIdx.x, b = blockIdx.x;
    int i = b * 256 + t;
    int lane = t & 31, w = t >> 5;
    int v = (i < NN) ? g_cnt[i] : 0;
    int inc = v;
#pragma unroll
    for (int o = 1; o < 32; o <<= 1) {
        int nv = __shfl_up_sync(0xffffffffu, inc, o);
        if (lane >= o) inc += nv;
    }
    if (lane == 31) ws[w] = inc;
    __syncthreads();
    if (t < 8) {
        int s = ws[t];
#pragma unroll
        for (int o = 1; o < 8; o <<= 1) {
            int nv = __shfl_up_sync(0x000000ffu, s, o);
            if (t >= o) s += nv;
        }
        ws[t] = s;
    }
    __syncthreads();
    int boff = (w > 0) ? ws[w - 1] : 0;
    if (i < NN) g_row[i] = inc - v + boff;   // block-local exclusive
    if (t == 255) g_bsum[b] = ws[7];
}

__global__ void k_scan2() {
    __shared__ int sm[512];
    int t = threadIdx.x;
    int me = (t < NB1) ? g_bsum[t] : 0;
    sm[t] = me;
    __syncthreads();
    for (int o = 1; o < 512; o <<= 1) {
        int v = (t >= o) ? sm[t - o] : 0;
        __syncthreads();
        sm[t] += v;
        __syncthreads();
    }
    if (t < NB1) g_bsum[t] = sm[t] - me;     // exclusive
}

__global__ void k_scan3() {
    int i = blockIdx.x * blockDim.x + threadIdx.x;
    if (i < NN) {
        int r = g_row[i] + g_bsum[blockIdx.x];
        g_row[i] = r;
        g_wpos[i] = r;
    }
    if (i == 0) g_row[NN] = ENL;
}

__global__ void k_scatter(const int* __restrict__ ei) {
    int e = blockIdx.x * blockDim.x + threadIdx.x;
    if (e >= ENL) return;
    int s, d; edge_sd(ei, e, s, d);
    int pos = atomicAdd(&g_wpos[d], 1);
    g_esrc[pos] = s;
}

// ---------------- pre-pass: W1^T -> fp16 ldmatrix-swizzled image ----------------
__global__ void k_prepB(const float* __restrict__ W1) {
    int t = blockIdx.x * blockDim.x + threadIdx.x;
    if (t >= FIN * F1) return;
    int n = t & 127, kg = t >> 7;           // W1[kg][n]
    __half h = __float2half_rn(W1[kg * F1 + n]);
    int kt = kg >> 6, kk = kg & 63;
    uint32_t byte = (uint32_t)(n * 128 + (((kk >> 3) ^ (n & 7)) * 16) + (kk & 7) * 2);
    g_Bh[kt * 8192 + (byte >> 1)] = h;
}

// ---------------- GEMM1: h1 = x @ W1 via mma.sync fp16 (+fused att projections) ----------------
// A single fp16 term; B single fp16.  smem: A [0,16K)  B buf0 [16K,32K)  B buf1 [32K,48K)
#define G1_SMEM 49152

__global__ __launch_bounds__(512) void k_gemm1(const float* __restrict__ x,
                                               const float* __restrict__ att_s,
                                               const float* __restrict__ att_d) {
    extern __shared__ __align__(1024) char smem[];
    const uint32_t sb = (uint32_t)__cvta_generic_to_shared(smem);
    const int tid  = threadIdx.x;
    const int lane = tid & 31, wid = tid >> 5;
    const int wm = wid & 3, wn = wid >> 2;
    const int row0 = blockIdx.x * 128;
    const int f4c = tid & 15, rb = tid >> 4;

    float acc[2][4][4];
#pragma unroll
    for (int a = 0; a < 2; a++)
#pragma unroll
        for (int b = 0; b < 4; b++)
#pragma unroll
            for (int c = 0; c < 4; c++) acc[a][b][c] = 0.f;

    float4 av[4];

    auto cpB = [&](int kt, int buf) {
        uint32_t dst = sb + 16384 + buf * 16384 + tid * 16;
        const char* p = (const char*)g_Bh + (size_t)kt * 16384 + tid * 16;
        cpasync16(dst,        p);
        cpasync16(dst + 8192, p + 8192);
        asm volatile("cp.async.commit_group;" ::: "memory");
    };
    auto ldA = [&](int kt) {
#pragma unroll
        for (int j = 0; j < 4; j++) {
            int gr = row0 + rb + 32 * j;
            av[j] = make_float4(0.f, 0.f, 0.f, 0.f);
            if (gr < NN) av[j] = *(const float4*)&x[(size_t)gr * FIN + kt * 64 + f4c * 4];
        }
    };
    auto stA = [&]() {
#pragma unroll
        for (int j = 0; j < 4; j++) {
            int m = rb + 32 * j;
            uint32_t byte = (uint32_t)(m * 128 + (((f4c >> 1) ^ (m & 7)) * 16) + (f4c & 1) * 8);
            float4 v = av[j];
            uint2 hw;
            __half2 p01 = __floats2half2_rn(v.x, v.y);
            __half2 p23 = __floats2half2_rn(v.z, v.w);
            hw.x = *(uint32_t*)&p01;
            hw.y = *(uint32_t*)&p23;
            *(uint2*)(smem + byte) = hw;
        }
    };

    cpB(0, 0);
    ldA(0);

    const int arow = wm * 32 + (lane & 15);
    const int brow = wn * 32 + (lane & 15);
    const int half = lane >> 4;

    for (int kt = 0; kt < 16; kt++) {
        __syncthreads();
        stA();
        if (kt < 15) { cpB(kt + 1, (kt + 1) & 1); ldA(kt + 1); }
        if (kt < 15) asm volatile("cp.async.wait_group 1;" ::: "memory");
        else         asm volatile("cp.async.wait_group 0;" ::: "memory");
        __syncthreads();

        const uint32_t sB = sb + 16384 + (kt & 1) * 16384;
#pragma unroll
        for (int ks = 0; ks < 4; ks++) {
            const int ch = 2 * ks + half;
            uint4 ah[2], bh[2];
#pragma unroll
            for (int mt = 0; mt < 2; mt++) {
                int m = arow + mt * 16;
                uint32_t off = (uint32_t)(m * 128 + ((ch ^ (m & 7)) * 16));
                ldsm4(ah[mt], sb + off);
            }
#pragma unroll
            for (int bp = 0; bp < 2; bp++) {
                int n = brow + bp * 16;
                uint32_t off = (uint32_t)(n * 128 + ((ch ^ (n & 7)) * 16));
                ldsm4(bh[bp], sB + off);
            }
#pragma unroll
            for (int mt = 0; mt < 2; mt++)
#pragma unroll
                for (int bp = 0; bp < 2; bp++) {
                    mma16816(acc[mt][bp * 2 + 0], ah[mt], bh[bp].x, bh[bp].z);
                    mma16816(acc[mt][bp * 2 + 1], ah[mt], bh[bp].y, bh[bp].w);
                }
        }
    }

    // ---- epilogue: write h1 (fp16) + fused attention projections ----
    const int q = lane >> 2, qp = lane & 3;
#pragma unroll
    for (int mt = 0; mt < 2; mt++) {
        int r0g = row0 + wm * 32 + mt * 16 + q;
        int r1g = r0g + 8;
#pragma unroll
        for (int nt = 0; nt < 4; nt++) {
            int c = wn * 32 + nt * 8 + qp * 2;
            float v0 = acc[mt][nt][0], v1 = acc[mt][nt][1];
            float v2 = acc[mt][nt][2], v3 = acc[mt][nt][3];
            if (r0g < NN) {
                __half2 hv = __floats2half2_rn(v0, v1);
                *(__half2*)&g_h1h[(size_t)r0g * F1 + c] = hv;
            }
            if (r1g < NN) {
                __half2 hv = __floats2half2_rn(v2, v3);
                *(__half2*)&g_h1h[(size_t)r1g * F1 + c] = hv;
            }
            float as0 = __ldg(&att_s[c]), as1 = __ldg(&att_s[c + 1]);
            float ad0 = __ldg(&att_d[c]), ad1 = __ldg(&att_d[c + 1]);
            float ps0 = v0 * as0 + v1 * as1, pd0 = v0 * ad0 + v1 * ad1;
            float ps1 = v2 * as0 + v3 * as1, pd1 = v2 * ad0 + v3 * ad1;
            ps0 += __shfl_xor_sync(~0u, ps0, 1); ps0 += __shfl_xor_sync(~0u, ps0, 2);
            pd0 += __shfl_xor_sync(~0u, pd0, 1); pd0 += __shfl_xor_sync(~0u, pd0, 2);
            ps1 += __shfl_xor_sync(~0u, ps1, 1); ps1 += __shfl_xor_sync(~0u, ps1, 2);
            pd1 += __shfl_xor_sync(~0u, pd1, 1); pd1 += __shfl_xor_sync(~0u, pd1, 2);
            if (qp == 0) {
                int h = wn * 4 + nt;
                if (r0g < NN) { g_asrc1[r0g * H1 + h] = ps0; g_adst1[r0g * H1 + h] = pd0; }
                if (r1g < NN) { g_asrc1[r1g * H1 + h] = ps1; g_adst1[r1g * H1 + h] = pd1; }
            }
        }
    }
}

// ---------------- layer-1: fused softmax-agg + bias + ELU + GEMM2 + att projections ----------------
// TWO warps per destination node (edge range split in half; partials combined in smem).
// Block 256 = 8 warps = 4 nodes. NN % 4 == 0 so no bounds guard needed.
__global__ __launch_bounds__(256) void k_agg1(const float* __restrict__ b1,
                                              const float* __restrict__ W2,
                                              const float* __restrict__ as2,
                                              const float* __restrict__ ad2) {
    __shared__ __align__(16) float sW[C2][F1];   // W2 transposed: sW[class][k]
    __shared__ float sas[C2], sad[C2];
    __shared__ float comb[4][32][5];             // partials from the odd warp
    int tid = threadIdx.x;
    for (int idx = tid; idx < F1 * C2; idx += 256) {
        int k = idx / C2, j = idx % C2;
        sW[j][k] = W2[idx];
    }
    if (tid < C2) { sas[tid] = as2[tid]; sad[tid] = ad2[tid]; }
    __syncthreads();

    int nd  = tid >> 6;          // node within block: 0..3
    int sub = (tid >> 5) & 1;    // which half of the edge range
    int l   = tid & 31;
    int n   = blockIdx.x * 4 + nd;
    int h   = l >> 1;
    int beg0 = g_row[n], end0 = g_row[n + 1];
    int halfc = (end0 - beg0) >> 1;
    int beg = sub ? (beg0 + halfc) : beg0;
    int end = sub ? end0 : (beg0 + halfc);
    float ad = g_adst1[n * H1 + h];
    float ax = 0.f, ay = 0.f, az = 0.f, aw = 0.f, wsum = 0.f;

    int e = beg;
    for (; e + 4 <= end; e += 4) {
        int s0 = __ldg(&g_esrc[e + 0]);
        int s1 = __ldg(&g_esrc[e + 1]);
        int s2 = __ldg(&g_esrc[e + 2]);
        int s3 = __ldg(&g_esrc[e + 3]);
        float a0 = __ldg(&g_asrc1[s0 * H1 + h]);
        float a1 = __ldg(&g_asrc1[s1 * H1 + h]);
        float a2 = __ldg(&g_asrc1[s2 * H1 + h]);
        float a3 = __ldg(&g_asrc1[s3 * H1 + h]);
        uint2 u0 = *(const uint2*)&g_h1h[(size_t)s0 * F1 + l * 4];
        uint2 u1 = *(const uint2*)&g_h1h[(size_t)s1 * F1 + l * 4];
        uint2 u2 = *(const uint2*)&g_h1h[(size_t)s2 * F1 + l * 4];
        uint2 u3 = *(const uint2*)&g_h1h[(size_t)s3 * F1 + l * 4];
        float w0 = __expf(lrelu(a0 + ad));
        float w1 = __expf(lrelu(a1 + ad));
        float w2 = __expf(lrelu(a2 + ad));
        float w3 = __expf(lrelu(a3 + ad));
        float2 f0a = __half22float2(*(__half2*)&u0.x), f0b = __half22float2(*(__half2*)&u0.y);
        float2 f1a = __half22float2(*(__half2*)&u1.x), f1b = __half22float2(*(__half2*)&u1.y);
        float2 f2a = __half22float2(*(__half2*)&u2.x), f2b = __half22float2(*(__half2*)&u2.y);
        float2 f3a = __half22float2(*(__half2*)&u3.x), f3b = __half22float2(*(__half2*)&u3.y);
        ax += w0 * f0a.x + w1 * f1a.x + w2 * f2a.x + w3 * f3a.x;
        ay += w0 * f0a.y + w1 * f1a.y + w2 * f2a.y + w3 * f3a.y;
        az += w0 * f0b.x + w1 * f1b.x + w2 * f2b.x + w3 * f3b.x;
        aw += w0 * f0b.y + w1 * f1b.y + w2 * f2b.y + w3 * f3b.y;
        wsum += (w0 + w1) + (w2 + w3);
    }
    for (; e < end; e++) {
        int s = __ldg(&g_esrc[e]);
        float as = __ldg(&g_asrc1[s * H1 + h]);
        float w = __expf(lrelu(as + ad));
        uint2 u = *(const uint2*)&g_h1h[(size_t)s * F1 + l * 4];
        float2 fa = __half22float2(*(__half2*)&u.x), fb = __half22float2(*(__half2*)&u.y);
        ax += w * fa.x; ay += w * fa.y; az += w * fb.x; aw += w * fb.y;
        wsum += w;
    }

    if (sub) {
        comb[nd][l][0] = ax; comb[nd][l][1] = ay;
        comb[nd][l][2] = az; comb[nd][l][3] = aw;
        comb[nd][l][4] = wsum;
    }
    __syncthreads();
    if (sub) return;
    ax += comb[nd][l][0]; ay += comb[nd][l][1];
    az += comb[nd][l][2]; aw += comb[nd][l][3];
    wsum += comb[nd][l][4];

    float inv = __fdividef(1.f, wsum + 1e-16f);
    float4 bb = *(const float4*)&b1[l * 4];
    float o0 = ax * inv + bb.x, o1 = ay * inv + bb.y;
    float o2 = az * inv + bb.z, o3 = aw * inv + bb.w;
    o0 = o0 > 0.f ? o0 : expm1f(o0);
    o1 = o1 > 0.f ? o1 : expm1f(o1);
    o2 = o2 > 0.f ? o2 : expm1f(o2);
    o3 = o3 > 0.f ? o3 : expm1f(o3);

    // ---- fused GEMM2: h2[n] = out1[n] @ W2 ----
    float mine = 0.f;
#pragma unroll
    for (int j = 0; j < C2; j++) {
        float4 w = *(const float4*)&sW[j][l * 4];
        float p = o0 * w.x + o1 * w.y + o2 * w.z + o3 * w.w;
#pragma unroll
        for (int o = 16; o; o >>= 1) p += __shfl_xor_sync(0xffffffffu, p, o);
        if (l == j) mine = p;
    }
    if (l < C2P) g_h2[n * C2P + l] = (l < C2) ? mine : 0.f;

    float psrc = (l < C2) ? mine * sas[l] : 0.f;
    float pdst = (l < C2) ? mine * sad[l] : 0.f;
#pragma unroll
    for (int o = 16; o; o >>= 1) {
        psrc += __shfl_xor_sync(0xffffffffu, psrc, o);
        pdst += __shfl_xor_sync(0xffffffffu, pdst, o);
    }
    if (l == 0) { g_asrc2[n] = psrc; g_adst2[n] = pdst; }
}

// ---------------- layer-2: fused softmax-agg + normalize + bias + log_softmax ----------------
// warp per destination node; lane l = class
__global__ __launch_bounds__(256) void k_agg2(const float* __restrict__ b2,
                                              float* __restrict__ out) {
    int n = blockIdx.x * 8 + (threadIdx.x >> 5);
    if (n >= NN) return;
    int l = threadIdx.x & 31;
    int beg = g_row[n], end = g_row[n + 1];
    float ad = g_adst2[n];
    float acc = 0.f, wsum = 0.f;
    int lc = (l < C2) ? l : 0;

    int e = beg;
    for (; e + 4 <= end; e += 4) {
        int s0 = __ldg(&g_esrc[e + 0]);
        int s1 = __ldg(&g_esrc[e + 1]);
        int s2 = __ldg(&g_esrc[e + 2]);
        int s3 = __ldg(&g_esrc[e + 3]);
        float a0 = __ldg(&g_asrc2[s0]);
        float a1 = __ldg(&g_asrc2[s1]);
        float a2 = __ldg(&g_asrc2[s2]);
        float a3 = __ldg(&g_asrc2[s3]);
        float v0 = __ldg(&g_h2[s0 * C2P + lc]);
        float v1 = __ldg(&g_h2[s1 * C2P + lc]);
        float v2 = __ldg(&g_h2[s2 * C2P + lc]);
        float v3 = __ldg(&g_h2[s3 * C2P + lc]);
        float w0 = __expf(lrelu(a0 + ad));
        float w1 = __expf(lrelu(a1 + ad));
        float w2 = __expf(lrelu(a2 + ad));
        float w3 = __expf(lrelu(a3 + ad));
        acc += w0 * v0 + w1 * v1 + w2 * v2 + w3 * v3;
        wsum += (w0 + w1) + (w2 + w3);
    }
    for (; e < end; e++) {
        int s = __ldg(&g_esrc[e]);
        float as = __ldg(&g_asrc2[s]);
        float w = __expf(lrelu(as + ad));
        acc += w * __ldg(&g_h2[s * C2P + lc]);
        wsum += w;
    }

    float val = __fdividef(acc, wsum + 1e-16f) + ((l < C2) ? b2[l] : 0.f);
    float z = (l < C2) ? val : -1e30f;
    float m = z;
#pragma unroll
    for (int o = 16; o; o >>= 1) m = fmaxf(m, __shfl_xor_sync(0xffffffffu, m, o));
    float ex = (l < C2) ? expf(z - m) : 0.f;
    float ssum = ex;
#pragma unroll
    for (int o = 16; o; o >>= 1) ssum += __shfl_xor_sync(0xffffffffu, ssum, o);
    float lse = m + logf(ssum);
    if (l < C2) out[n * C2 + l] = z - lse;
}

// ---------------- launch ----------------
extern "C" void kernel_launch(void* const* d_in, const int* in_sizes, int n_in,
                              void* d_out, int out_size) {
    const float* x   = (const float*)d_in[0];
    const int*   ei  = (const int*)  d_in[1];
    const float* W1  = (const float*)d_in[2];
    const float* as1 = (const float*)d_in[3];
    const float* ad1 = (const float*)d_in[4];
    const float* b1  = (const float*)d_in[5];
    const float* W2  = (const float*)d_in[6];
    const float* as2 = (const float*)d_in[7];
    const float* ad2 = (const float*)d_in[8];
    const float* b2  = (const float*)d_in[9];
    float* out = (float*)d_out;

    static int inited = 0;
    static cudaStream_t s2;
    static cudaEvent_t evFork, evJoin;
    if (!inited) {
        cudaFuncSetAttribute(k_gemm1, cudaFuncAttributeMaxDynamicSharedMemorySize, G1_SMEM);
        cudaStreamCreateWithFlags(&s2, cudaStreamNonBlocking);
        cudaEventCreateWithFlags(&evFork, cudaEventDisableTiming);
        cudaEventCreateWithFlags(&evJoin, cudaEventDisableTiming);
        inited = 1;
    }

    // fork: CSR chain (depends only on ei) runs on s2, overlapped with prepB+gemm1
    cudaEventRecord(evFork, 0);
    cudaStreamWaitEvent(s2, evFork, 0);

    k_init<<<NB1, 256, 0, s2>>>();
    k_hist<<<(ENL + 255) / 256, 256, 0, s2>>>(ei);
    k_scan1<<<NB1, 256, 0, s2>>>();
    k_scan2<<<1, 512, 0, s2>>>();
    k_scan3<<<NB1, 256, 0, s2>>>();
    k_scatter<<<(ENL + 255) / 256, 256, 0, s2>>>(ei);
    cudaEventRecord(evJoin, s2);

    k_prepB<<<(FIN * F1 + 255) / 256, 256>>>(W1);
    k_gemm1<<<(NN + 127) / 128, 512, G1_SMEM>>>(x, as1, ad1);

    // join: agg1 needs both the CSR and gemm1 results
    cudaStreamWaitEvent(0, evJoin, 0);
    k_agg1<<<NN / 4, 256>>>(b1, W2, as2, ad2);
    k_agg2<<<(NN + 7) / 8, 256>>>(b2, out);
}

// round 16
// speedup vs baseline: 1.1432x; 1.1432x over previous
#include <cuda_runtime.h>
#include <cuda_fp16.h>
#include <math.h>
#include <stdint.h>

#define NN   100000
#define EE   1600000
#define ENL  1700000     // edges + self loops
#define FIN  1024
#define F1   128         // H1*C1
#define H1   16
#define C2   19
#define C2P  20
#define NB1  ((NN + 255) / 256)   // 391 scan blocks

// ---------------- scratch (device globals; no allocation allowed) ----------------
__device__ __half   g_h1h  [(size_t)NN * F1];   // h1 in fp16 (halves agg1 gather traffic)
__device__ float    g_asrc1[NN * H1];
__device__ float    g_adst1[NN * H1];
__device__ float    g_h2   [NN * C2P];
__device__ float    g_asrc2[NN];
__device__ float    g_adst2[NN];
// CSR by destination
__device__ int      g_cnt  [NN];
__device__ int      g_row  [NN + 1];
__device__ int      g_wpos [NN];
__device__ int      g_bsum [512];
__device__ int      g_esrc [ENL];
// W1^T in fp16, pre-laid-out in the smem/ldmatrix layout:
// tile kt = [128 n-rows][64 k-cols] fp16, 128B rows, chunk ^= (row&7) swizzle.
__device__ __align__(16) __half g_Bh[16 * 8192];

// ---------------- helpers ----------------
__device__ __forceinline__ float lrelu(float x) { return x >= 0.f ? x : 0.2f * x; }

__device__ __forceinline__ void edge_sd(const int* __restrict__ ei, int e, int& s, int& d) {
    if (e < EE) { s = ei[e]; d = ei[EE + e]; }
    else        { s = e - EE; d = s; }
}

__device__ __forceinline__ void ldsm4(uint4& r, uint32_t addr) {
    asm volatile("ldmatrix.sync.aligned.m8n8.x4.shared.b16 {%0,%1,%2,%3}, [%4];"
                 : "=r"(r.x), "=r"(r.y), "=r"(r.z), "=r"(r.w) : "r"(addr));
}

__device__ __forceinline__ void mma16816(float* d, const uint4& a, uint32_t b0, uint32_t b1) {
    asm volatile(
        "mma.sync.aligned.m16n8k16.row.col.f32.f16.f16.f32 "
        "{%0,%1,%2,%3}, {%4,%5,%6,%7}, {%8,%9}, {%0,%1,%2,%3};"
        : "+f"(d[0]), "+f"(d[1]), "+f"(d[2]), "+f"(d[3])
        : "r"(a.x), "r"(a.y), "r"(a.z), "r"(a.w), "r"(b0), "r"(b1));
}

__device__ __forceinline__ void cpasync16(uint32_t dst, const void* src) {
    asm volatile("cp.async.cg.shared.global [%0], [%1], 16;" :: "r"(dst), "l"(src) : "memory");
}

// ---------------- init: zero histogram only ----------------
__global__ void k_init() {
    int i = blockIdx.x * blockDim.x + threadIdx.x;
    if (i < NN) g_cnt[i] = 0;
}

// ---------------- CSR build ----------------
__global__ void k_hist(const int* __restrict__ ei) {
    int e = blockIdx.x * blockDim.x + threadIdx.x;
    if (e >= ENL) return;
    int s, d; edge_sd(ei, e, s, d);
    atomicAdd(&g_cnt[d], 1);
}

__global__ void k_scan1() {
    __shared__ int ws[8];
    int t = threadIdx.x, b = blockIdx.x;
    int i = b * 256 + t;
    int lane = t & 31, w = t >> 5;
    int v = (i < NN) ? g_cnt[i] : 0;
    int inc = v;
#pragma unroll
    for (int o = 1; o < 32; o <<= 1) {
        int nv = __shfl_up_sync(0xffffffffu, inc, o);
        if (lane >= o) inc += nv;
    }
    if (lane == 31) ws[w] = inc;
    __syncthreads();
    if (t < 8) {
        int s = ws[t];
#pragma unroll
        for (int o = 1; o < 8; o <<= 1) {
            int nv = __shfl_up_sync(0x000000ffu, s, o);
            if (t >= o) s += nv;
        }
        ws[t] = s;
    }
    __syncthreads();
    int boff = (w > 0) ? ws[w - 1] : 0;
    if (i < NN) g_row[i] = inc - v + boff;   // block-local exclusive
    if (t == 255) g_bsum[b] = ws[7];
}

__global__ void k_scan2() {
    __shared__ int sm[512];
    int t = threadIdx.x;
    int me = (t < NB1) ? g_bsum[t] : 0;
    sm[t] = me;
    __syncthreads();
    for (int o = 1; o < 512; o <<= 1) {
        int v = (t >= o) ? sm[t - o] : 0;
        __syncthreads();
        sm[t] += v;
        __syncthreads();
    }
    if (t < NB1) g_bsum[t] = sm[t] - me;     // exclusive
}

__global__ void k_scan3() {
    int i = blockIdx.x * blockDim.x + threadIdx.x;
    if (i < NN) {
        int r = g_row[i] + g_bsum[blockIdx.x];
        g_row[i] = r;
        g_wpos[i] = r;
    }
    if (i == 0) g_row[NN] = ENL;
}

__global__ void k_scatter(const int* __restrict__ ei) {
    int e = blockIdx.x * blockDim.x + threadIdx.x;
    if (e >= ENL) return;
    int s, d; edge_sd(ei, e, s, d);
    int pos = atomicAdd(&g_wpos[d], 1);
    g_esrc[pos] = s;
}

// ---------------- pre-pass: W1^T -> fp16 ldmatrix-swizzled image ----------------
__global__ void k_prepB(const float* __restrict__ W1) {
    int t = blockIdx.x * blockDim.x + threadIdx.x;
    if (t >= FIN * F1) return;
    int n = t & 127, kg = t >> 7;           // W1[kg][n]
    __half h = __float2half_rn(W1[kg * F1 + n]);
    int kt = kg >> 6, kk = kg & 63;
    uint32_t byte = (uint32_t)(n * 128 + (((kk >> 3) ^ (n & 7)) * 16) + (kk & 7) * 2);
    g_Bh[kt * 8192 + (byte >> 1)] = h;
}

// ---------------- GEMM1: h1 = x @ W1 via mma.sync fp16 (+fused att projections) ----------------
// A single fp16 term; B single fp16.  smem: A [0,16K)  B buf0 [16K,32K)  B buf1 [32K,48K)
#define G1_SMEM 49152

__global__ __launch_bounds__(512) void k_gemm1(const float* __restrict__ x,
                                               const float* __restrict__ att_s,
                                               const float* __restrict__ att_d) {
    extern __shared__ __align__(1024) char smem[];
    const uint32_t sb = (uint32_t)__cvta_generic_to_shared(smem);
    const int tid  = threadIdx.x;
    const int lane = tid & 31, wid = tid >> 5;
    const int wm = wid & 3, wn = wid >> 2;
    const int row0 = blockIdx.x * 128;
    const int f4c = tid & 15, rb = tid >> 4;

    float acc[2][4][4];
#pragma unroll
    for (int a = 0; a < 2; a++)
#pragma unroll
        for (int b = 0; b < 4; b++)
#pragma unroll
            for (int c = 0; c < 4; c++) acc[a][b][c] = 0.f;

    float4 av[4];

    auto cpB = [&](int kt, int buf) {
        uint32_t dst = sb + 16384 + buf * 16384 + tid * 16;
        const char* p = (const char*)g_Bh + (size_t)kt * 16384 + tid * 16;
        cpasync16(dst,        p);
        cpasync16(dst + 8192, p + 8192);
        asm volatile("cp.async.commit_group;" ::: "memory");
    };
    auto ldA = [&](int kt) {
#pragma unroll
        for (int j = 0; j < 4; j++) {
            int gr = row0 + rb + 32 * j;
            av[j] = make_float4(0.f, 0.f, 0.f, 0.f);
            if (gr < NN) av[j] = *(const float4*)&x[(size_t)gr * FIN + kt * 64 + f4c * 4];
        }
    };
    auto stA = [&]() {
#pragma unroll
        for (int j = 0; j < 4; j++) {
            int m = rb + 32 * j;
            uint32_t byte = (uint32_t)(m * 128 + (((f4c >> 1) ^ (m & 7)) * 16) + (f4c & 1) * 8);
            float4 v = av[j];
            uint2 hw;
            __half2 p01 = __floats2half2_rn(v.x, v.y);
            __half2 p23 = __floats2half2_rn(v.z, v.w);
            hw.x = *(uint32_t*)&p01;
            hw.y = *(uint32_t*)&p23;
            *(uint2*)(smem + byte) = hw;
        }
    };

    cpB(0, 0);
    ldA(0);

    const int arow = wm * 32 + (lane & 15);
    const int brow = wn * 32 + (lane & 15);
    const int half = lane >> 4;

    for (int kt = 0; kt < 16; kt++) {
        __syncthreads();
        stA();
        if (kt < 15) { cpB(kt + 1, (kt + 1) & 1); ldA(kt + 1); }
        if (kt < 15) asm volatile("cp.async.wait_group 1;" ::: "memory");
        else         asm volatile("cp.async.wait_group 0;" ::: "memory");
        __syncthreads();

        const uint32_t sB = sb + 16384 + (kt & 1) * 16384;
#pragma unroll
        for (int ks = 0; ks < 4; ks++) {
            const int ch = 2 * ks + half;
            uint4 ah[2], bh[2];
#pragma unroll
            for (int mt = 0; mt < 2; mt++) {
                int m = arow + mt * 16;
                uint32_t off = (uint32_t)(m * 128 + ((ch ^ (m & 7)) * 16));
                ldsm4(ah[mt], sb + off);
            }
#pragma unroll
            for (int bp = 0; bp < 2; bp++) {
                int n = brow + bp * 16;
                uint32_t off = (uint32_t)(n * 128 + ((ch ^ (n & 7)) * 16));
                ldsm4(bh[bp], sB + off);
            }
#pragma unroll
            for (int mt = 0; mt < 2; mt++)
#pragma unroll
                for (int bp = 0; bp < 2; bp++) {
                    mma16816(acc[mt][bp * 2 + 0], ah[mt], bh[bp].x, bh[bp].z);
                    mma16816(acc[mt][bp * 2 + 1], ah[mt], bh[bp].y, bh[bp].w);
                }
        }
    }

    // ---- epilogue: write h1 (fp16) + fused attention projections ----
    const int q = lane >> 2, qp = lane & 3;
#pragma unroll
    for (int mt = 0; mt < 2; mt++) {
        int r0g = row0 + wm * 32 + mt * 16 + q;
        int r1g = r0g + 8;
#pragma unroll
        for (int nt = 0; nt < 4; nt++) {
            int c = wn * 32 + nt * 8 + qp * 2;
            float v0 = acc[mt][nt][0], v1 = acc[mt][nt][1];
            float v2 = acc[mt][nt][2], v3 = acc[mt][nt][3];
            if (r0g < NN) {
                __half2 hv = __floats2half2_rn(v0, v1);
                *(__half2*)&g_h1h[(size_t)r0g * F1 + c] = hv;
            }
            if (r1g < NN) {
                __half2 hv = __floats2half2_rn(v2, v3);
                *(__half2*)&g_h1h[(size_t)r1g * F1 + c] = hv;
            }
            float as0 = __ldg(&att_s[c]), as1 = __ldg(&att_s[c + 1]);
            float ad0 = __ldg(&att_d[c]), ad1 = __ldg(&att_d[c + 1]);
            float ps0 = v0 * as0 + v1 * as1, pd0 = v0 * ad0 + v1 * ad1;
            float ps1 = v2 * as0 + v3 * as1, pd1 = v2 * ad0 + v3 * ad1;
            ps0 += __shfl_xor_sync(~0u, ps0, 1); ps0 += __shfl_xor_sync(~0u, ps0, 2);
            pd0 += __shfl_xor_sync(~0u, pd0, 1); pd0 += __shfl_xor_sync(~0u, pd0, 2);
            ps1 += __shfl_xor_sync(~0u, ps1, 1); ps1 += __shfl_xor_sync(~0u, ps1, 2);
            pd1 += __shfl_xor_sync(~0u, pd1, 1); pd1 += __shfl_xor_sync(~0u, pd1, 2);
            if (qp == 0) {
                int h = wn * 4 + nt;
                if (r0g < NN) { g_asrc1[r0g * H1 + h] = ps0; g_adst1[r0g * H1 + h] = pd0; }
                if (r1g < NN) { g_asrc1[r1g * H1 + h] = ps1; g_adst1[r1g * H1 + h] = pd1; }
            }
        }
    }
}

// ---------------- layer-1: fused softmax-agg + bias + ELU + GEMM2 + att projections ----------------
// warp per destination node (R14 structure); 8-wide unrolled gather loop.
__global__ __launch_bounds__(256) void k_agg1(const float* __restrict__ b1,
                                              const float* __restrict__ W2,
                                              const float* __restrict__ as2,
                                              const float* __restrict__ ad2) {
    __shared__ __align__(16) float sW[C2][F1];   // W2 transposed: sW[class][k]
    __shared__ float sas[C2], sad[C2];
    int tid = threadIdx.x;
    for (int idx = tid; idx < F1 * C2; idx += 256) {
        int k = idx / C2, j = idx % C2;
        sW[j][k] = W2[idx];
    }
    if (tid < C2) { sas[tid] = as2[tid]; sad[tid] = ad2[tid]; }
    __syncthreads();

    int n = blockIdx.x * 8 + (tid >> 5);
    if (n >= NN) return;
    int l = tid & 31;
    int h = l >> 1;
    int beg = g_row[n], end = g_row[n + 1];
    float ad = g_adst1[n * H1 + h];
    float ax = 0.f, ay = 0.f, az = 0.f, aw = 0.f, wsum = 0.f;

    int e = beg;
    for (; e + 8 <= end; e += 8) {
        int s[8];
#pragma unroll
        for (int j = 0; j < 8; j++) s[j] = __ldg(&g_esrc[e + j]);
        float a[8];
#pragma unroll
        for (int j = 0; j < 8; j++) a[j] = __ldg(&g_asrc1[s[j] * H1 + h]);
        uint2 u[8];
#pragma unroll
        for (int j = 0; j < 8; j++) u[j] = *(const uint2*)&g_h1h[(size_t)s[j] * F1 + l * 4];
#pragma unroll
        for (int j = 0; j < 8; j++) {
            float w = __expf(lrelu(a[j] + ad));
            float2 fa = __half22float2(*(__half2*)&u[j].x);
            float2 fb = __half22float2(*(__half2*)&u[j].y);
            ax += w * fa.x; ay += w * fa.y; az += w * fb.x; aw += w * fb.y;
            wsum += w;
        }
    }
    for (; e < end; e++) {
        int s = __ldg(&g_esrc[e]);
        float as = __ldg(&g_asrc1[s * H1 + h]);
        float w = __expf(lrelu(as + ad));
        uint2 u = *(const uint2*)&g_h1h[(size_t)s * F1 + l * 4];
        float2 fa = __half22float2(*(__half2*)&u.x), fb = __half22float2(*(__half2*)&u.y);
        ax += w * fa.x; ay += w * fa.y; az += w * fb.x; aw += w * fb.y;
        wsum += w;
    }

    float inv = __fdividef(1.f, wsum + 1e-16f);
    float4 bb = *(const float4*)&b1[l * 4];
    float o0 = ax * inv + bb.x, o1 = ay * inv + bb.y;
    float o2 = az * inv + bb.z, o3 = aw * inv + bb.w;
    o0 = o0 > 0.f ? o0 : expm1f(o0);
    o1 = o1 > 0.f ? o1 : expm1f(o1);
    o2 = o2 > 0.f ? o2 : expm1f(o2);
    o3 = o3 > 0.f ? o3 : expm1f(o3);

    // ---- fused GEMM2: h2[n] = out1[n] @ W2 ----
    float mine = 0.f;
#pragma unroll
    for (int j = 0; j < C2; j++) {
        float4 w = *(const float4*)&sW[j][l * 4];
        float p = o0 * w.x + o1 * w.y + o2 * w.z + o3 * w.w;
#pragma unroll
        for (int o = 16; o; o >>= 1) p += __shfl_xor_sync(0xffffffffu, p, o);
        if (l == j) mine = p;
    }
    if (l < C2P) g_h2[n * C2P + l] = (l < C2) ? mine : 0.f;

    float psrc = (l < C2) ? mine * sas[l] : 0.f;
    float pdst = (l < C2) ? mine * sad[l] : 0.f;
#pragma unroll
    for (int o = 16; o; o >>= 1) {
        psrc += __shfl_xor_sync(0xffffffffu, psrc, o);
        pdst += __shfl_xor_sync(0xffffffffu, pdst, o);
    }
    if (l == 0) { g_asrc2[n] = psrc; g_adst2[n] = pdst; }
}

// ---------------- layer-2: fused softmax-agg + normalize + bias + log_softmax ----------------
// warp per destination node; lane l = class; 8-wide unrolled gather loop.
__global__ __launch_bounds__(256) void k_agg2(const float* __restrict__ b2,
                                              float* __restrict__ out) {
    int n = blockIdx.x * 8 + (threadIdx.x >> 5);
    if (n >= NN) return;
    int l = threadIdx.x & 31;
    int beg = g_row[n], end = g_row[n + 1];
    float ad = g_adst2[n];
    float acc = 0.f, wsum = 0.f;
    int lc = (l < C2) ? l : 0;

    int e = beg;
    for (; e + 8 <= end; e += 8) {
        int s[8];
#pragma unroll
        for (int j = 0; j < 8; j++) s[j] = __ldg(&g_esrc[e + j]);
        float a[8], v[8];
#pragma unroll
        for (int j = 0; j < 8; j++) a[j] = __ldg(&g_asrc2[s[j]]);
#pragma unroll
        for (int j = 0; j < 8; j++) v[j] = __ldg(&g_h2[s[j] * C2P + lc]);
#pragma unroll
        for (int j = 0; j < 8; j++) {
            float w = __expf(lrelu(a[j] + ad));
            acc += w * v[j];
            wsum += w;
        }
    }
    for (; e < end; e++) {
        int s = __ldg(&g_esrc[e]);
        float as = __ldg(&g_asrc2[s]);
        float w = __expf(lrelu(as + ad));
        acc += w * __ldg(&g_h2[s * C2P + lc]);
        wsum += w;
    }

    float val = __fdividef(acc, wsum + 1e-16f) + ((l < C2) ? b2[l] : 0.f);
    float z = (l < C2) ? val : -1e30f;
    float m = z;
#pragma unroll
    for (int o = 16; o; o >>= 1) m = fmaxf(m, __shfl_xor_sync(0xffffffffu, m, o));
    float ex = (l < C2) ? expf(z - m) : 0.f;
    float ssum = ex;
#pragma unroll
    for (int o = 16; o; o >>= 1) ssum += __shfl_xor_sync(0xffffffffu, ssum, o);
    float lse = m + logf(ssum);
    if (l < C2) out[n * C2 + l] = z - lse;
}

// ---------------- launch ----------------
extern "C" void kernel_launch(void* const* d_in, const int* in_sizes, int n_in,
                              void* d_out, int out_size) {
    const float* x   = (const float*)d_in[0];
    const int*   ei  = (const int*)  d_in[1];
    const float* W1  = (const float*)d_in[2];
    const float* as1 = (const float*)d_in[3];
    const float* ad1 = (const float*)d_in[4];
    const float* b1  = (const float*)d_in[5];
    const float* W2  = (const float*)d_in[6];
    const float* as2 = (const float*)d_in[7];
    const float* ad2 = (const float*)d_in[8];
    const float* b2  = (const float*)d_in[9];
    float* out = (float*)d_out;

    static int inited = 0;
    static cudaStream_t s2;
    static cudaEvent_t evFork, evJoin;
    if (!inited) {
        cudaFuncSetAttribute(k_gemm1, cudaFuncAttributeMaxDynamicSharedMemorySize, G1_SMEM);
        cudaStreamCreateWithFlags(&s2, cudaStreamNonBlocking);
        cudaEventCreateWithFlags(&evFork, cudaEventDisableTiming);
        cudaEventCreateWithFlags(&evJoin, cudaEventDisableTiming);
        inited = 1;
    }

    // fork: CSR chain (depends only on ei) runs on s2, overlapped with prepB+gemm1
    cudaEventRecord(evFork, 0);
    cudaStreamWaitEvent(s2, evFork, 0);

    k_init<<<NB1, 256, 0, s2>>>();
    k_hist<<<(ENL + 255) / 256, 256, 0, s2>>>(ei);
    k_scan1<<<NB1, 256, 0, s2>>>();
    k_scan2<<<1, 512, 0, s2>>>();
    k_scan3<<<NB1, 256, 0, s2>>>();
    k_scatter<<<(ENL + 255) / 256, 256, 0, s2>>>(ei);
    cudaEventRecord(evJoin, s2);

    k_prepB<<<(FIN * F1 + 255) / 256, 256>>>(W1);
    k_gemm1<<<(NN + 127) / 128, 512, G1_SMEM>>>(x, as1, ad1);

    // join: agg1 needs both the CSR and gemm1 results
    cudaStreamWaitEvent(0, evJoin, 0);
    k_agg1<<<(NN + 7) / 8, 256>>>(b1, W2, as2, ad2);
    k_agg2<<<(NN + 7) / 8, 256>>>(b2, out);
}

// round 17
// speedup vs baseline: 1.1902x; 1.0411x over previous
#include <cuda_runtime.h>
#include <cuda_fp16.h>
#include <math.h>
#include <stdint.h>

#define NN   100000
#define EE   1600000
#define ENL  1700000     // edges + self loops
#define FIN  1024
#define F1   128         // H1*C1
#define H1   16
#define C2   19
#define C2P  20
#define NB1  ((NN + 255) / 256)   // 391 scan blocks

// ---------------- scratch (device globals; no allocation allowed) ----------------
__device__ __half   g_h1h  [(size_t)NN * F1];   // h1 in fp16 (halves agg1 gather traffic)
__device__ float    g_asrc1[NN * H1];
__device__ float    g_adst1[NN * H1];
__device__ __half   g_h2h  [NN * C2P];          // h2 in fp16 (halves agg2 gather traffic)
__device__ float    g_asrc2[NN];
__device__ float    g_adst2[NN];
// CSR by destination
__device__ int      g_cnt  [NN];
__device__ int      g_row  [NN + 1];
__device__ int      g_wpos [NN];
__device__ int      g_bsum [512];
__device__ int      g_esrc [ENL];
// W1^T in fp16, pre-laid-out in the smem/ldmatrix layout:
// tile kt = [128 n-rows][64 k-cols] fp16, 128B rows, chunk ^= (row&7) swizzle.
__device__ __align__(16) __half g_Bh[16 * 8192];

// ---------------- helpers ----------------
__device__ __forceinline__ float lrelu(float x) { return x >= 0.f ? x : 0.2f * x; }

__device__ __forceinline__ void edge_sd(const int* __restrict__ ei, int e, int& s, int& d) {
    if (e < EE) { s = ei[e]; d = ei[EE + e]; }
    else        { s = e - EE; d = s; }
}

__device__ __forceinline__ void ldsm4(uint4& r, uint32_t addr) {
    asm volatile("ldmatrix.sync.aligned.m8n8.x4.shared.b16 {%0,%1,%2,%3}, [%4];"
                 : "=r"(r.x), "=r"(r.y), "=r"(r.z), "=r"(r.w) : "r"(addr));
}

__device__ __forceinline__ void mma16816(float* d, const uint4& a, uint32_t b0, uint32_t b1) {
    asm volatile(
        "mma.sync.aligned.m16n8k16.row.col.f32.f16.f16.f32 "
        "{%0,%1,%2,%3}, {%4,%5,%6,%7}, {%8,%9}, {%0,%1,%2,%3};"
        : "+f"(d[0]), "+f"(d[1]), "+f"(d[2]), "+f"(d[3])
        : "r"(a.x), "r"(a.y), "r"(a.z), "r"(a.w), "r"(b0), "r"(b1));
}

__device__ __forceinline__ void cpasync16(uint32_t dst, const void* src) {
    asm volatile("cp.async.cg.shared.global [%0], [%1], 16;" :: "r"(dst), "l"(src) : "memory");
}

// ---------------- init: zero histogram only ----------------
__global__ void k_init() {
    int i = blockIdx.x * blockDim.x + threadIdx.x;
    if (i < NN) g_cnt[i] = 0;
}

// ---------------- CSR build ----------------
__global__ void k_hist(const int* __restrict__ ei) {
    int e = blockIdx.x * blockDim.x + threadIdx.x;
    if (e >= ENL) return;
    int s, d; edge_sd(ei, e, s, d);
    atomicAdd(&g_cnt[d], 1);
}

__global__ void k_scan1() {
    __shared__ int ws[8];
    int t = threadIdx.x, b = blockIdx.x;
    int i = b * 256 + t;
    int lane = t & 31, w = t >> 5;
    int v = (i < NN) ? g_cnt[i] : 0;
    int inc = v;
#pragma unroll
    for (int o = 1; o < 32; o <<= 1) {
        int nv = __shfl_up_sync(0xffffffffu, inc, o);
        if (lane >= o) inc += nv;
    }
    if (lane == 31) ws[w] = inc;
    __syncthreads();
    if (t < 8) {
        int s = ws[t];
#pragma unroll
        for (int o = 1; o < 8; o <<= 1) {
            int nv = __shfl_up_sync(0x000000ffu, s, o);
            if (t >= o) s += nv;
        }
        ws[t] = s;
    }
    __syncthreads();
    int boff = (w > 0) ? ws[w - 1] : 0;
    if (i < NN) g_row[i] = inc - v + boff;   // block-local exclusive
    if (t == 255) g_bsum[b] = ws[7];
}

__global__ void k_scan2() {
    __shared__ int sm[512];
    int t = threadIdx.x;
    int me = (t < NB1) ? g_bsum[t] : 0;
    sm[t] = me;
    __syncthreads();
    for (int o = 1; o < 512; o <<= 1) {
        int v = (t >= o) ? sm[t - o] : 0;
        __syncthreads();
        sm[t] += v;
        __syncthreads();
    }
    if (t < NB1) g_bsum[t] = sm[t] - me;     // exclusive
}

__global__ void k_scan3() {
    int i = blockIdx.x * blockDim.x + threadIdx.x;
    if (i < NN) {
        int r = g_row[i] + g_bsum[blockIdx.x];
        g_row[i] = r;
        g_wpos[i] = r;
    }
    if (i == 0) g_row[NN] = ENL;
}

__global__ void k_scatter(const int* __restrict__ ei) {
    int e = blockIdx.x * blockDim.x + threadIdx.x;
    if (e >= ENL) return;
    int s, d; edge_sd(ei, e, s, d);
    int pos = atomicAdd(&g_wpos[d], 1);
    g_esrc[pos] = s;
}

// ---------------- pre-pass: W1^T -> fp16 ldmatrix-swizzled image ----------------
__global__ void k_prepB(const float* __restrict__ W1) {
    int t = blockIdx.x * blockDim.x + threadIdx.x;
    if (t >= FIN * F1) return;
    int n = t & 127, kg = t >> 7;           // W1[kg][n]
    __half h = __float2half_rn(W1[kg * F1 + n]);
    int kt = kg >> 6, kk = kg & 63;
    uint32_t byte = (uint32_t)(n * 128 + (((kk >> 3) ^ (n & 7)) * 16) + (kk & 7) * 2);
    g_Bh[kt * 8192 + (byte >> 1)] = h;
}

// ---------------- GEMM1: h1 = x @ W1 via mma.sync fp16 (+fused att projections) ----------------
// A single fp16 term; B single fp16.  smem: A [0,16K)  B buf0 [16K,32K)  B buf1 [32K,48K)
#define G1_SMEM 49152

__global__ __launch_bounds__(512) void k_gemm1(const float* __restrict__ x,
                                               const float* __restrict__ att_s,
                                               const float* __restrict__ att_d) {
    extern __shared__ __align__(1024) char smem[];
    const uint32_t sb = (uint32_t)__cvta_generic_to_shared(smem);
    const int tid  = threadIdx.x;
    const int lane = tid & 31, wid = tid >> 5;
    const int wm = wid & 3, wn = wid >> 2;
    const int row0 = blockIdx.x * 128;
    const int f4c = tid & 15, rb = tid >> 4;

    float acc[2][4][4];
#pragma unroll
    for (int a = 0; a < 2; a++)
#pragma unroll
        for (int b = 0; b < 4; b++)
#pragma unroll
            for (int c = 0; c < 4; c++) acc[a][b][c] = 0.f;

    float4 av[4];

    auto cpB = [&](int kt, int buf) {
        uint32_t dst = sb + 16384 + buf * 16384 + tid * 16;
        const char* p = (const char*)g_Bh + (size_t)kt * 16384 + tid * 16;
        cpasync16(dst,        p);
        cpasync16(dst + 8192, p + 8192);
        asm volatile("cp.async.commit_group;" ::: "memory");
    };
    auto ldA = [&](int kt) {
#pragma unroll
        for (int j = 0; j < 4; j++) {
            int gr = row0 + rb + 32 * j;
            av[j] = make_float4(0.f, 0.f, 0.f, 0.f);
            if (gr < NN) av[j] = *(const float4*)&x[(size_t)gr * FIN + kt * 64 + f4c * 4];
        }
    };
    auto stA = [&]() {
#pragma unroll
        for (int j = 0; j < 4; j++) {
            int m = rb + 32 * j;
            uint32_t byte = (uint32_t)(m * 128 + (((f4c >> 1) ^ (m & 7)) * 16) + (f4c & 1) * 8);
            float4 v = av[j];
            uint2 hw;
            __half2 p01 = __floats2half2_rn(v.x, v.y);
            __half2 p23 = __floats2half2_rn(v.z, v.w);
            hw.x = *(uint32_t*)&p01;
            hw.y = *(uint32_t*)&p23;
            *(uint2*)(smem + byte) = hw;
        }
    };

    cpB(0, 0);
    ldA(0);

    const int arow = wm * 32 + (lane & 15);
    const int brow = wn * 32 + (lane & 15);
    const int half = lane >> 4;

    for (int kt = 0; kt < 16; kt++) {
        __syncthreads();
        stA();
        if (kt < 15) { cpB(kt + 1, (kt + 1) & 1); ldA(kt + 1); }
        if (kt < 15) asm volatile("cp.async.wait_group 1;" ::: "memory");
        else         asm volatile("cp.async.wait_group 0;" ::: "memory");
        __syncthreads();

        const uint32_t sB = sb + 16384 + (kt & 1) * 16384;
#pragma unroll
        for (int ks = 0; ks < 4; ks++) {
            const int ch = 2 * ks + half;
            uint4 ah[2], bh[2];
#pragma unroll
            for (int mt = 0; mt < 2; mt++) {
                int m = arow + mt * 16;
                uint32_t off = (uint32_t)(m * 128 + ((ch ^ (m & 7)) * 16));
                ldsm4(ah[mt], sb + off);
            }
#pragma unroll
            for (int bp = 0; bp < 2; bp++) {
                int n = brow + bp * 16;
                uint32_t off = (uint32_t)(n * 128 + ((ch ^ (n & 7)) * 16));
                ldsm4(bh[bp], sB + off);
            }
#pragma unroll
            for (int mt = 0; mt < 2; mt++)
#pragma unroll
                for (int bp = 0; bp < 2; bp++) {
                    mma16816(acc[mt][bp * 2 + 0], ah[mt], bh[bp].x, bh[bp].z);
                    mma16816(acc[mt][bp * 2 + 1], ah[mt], bh[bp].y, bh[bp].w);
                }
        }
    }

    // ---- epilogue: write h1 (fp16) + fused attention projections ----
    const int q = lane >> 2, qp = lane & 3;
#pragma unroll
    for (int mt = 0; mt < 2; mt++) {
        int r0g = row0 + wm * 32 + mt * 16 + q;
        int r1g = r0g + 8;
#pragma unroll
        for (int nt = 0; nt < 4; nt++) {
            int c = wn * 32 + nt * 8 + qp * 2;
            float v0 = acc[mt][nt][0], v1 = acc[mt][nt][1];
            float v2 = acc[mt][nt][2], v3 = acc[mt][nt][3];
            if (r0g < NN) {
                __half2 hv = __floats2half2_rn(v0, v1);
                *(__half2*)&g_h1h[(size_t)r0g * F1 + c] = hv;
            }
            if (r1g < NN) {
                __half2 hv = __floats2half2_rn(v2, v3);
                *(__half2*)&g_h1h[(size_t)r1g * F1 + c] = hv;
            }
            float as0 = __ldg(&att_s[c]), as1 = __ldg(&att_s[c + 1]);
            float ad0 = __ldg(&att_d[c]), ad1 = __ldg(&att_d[c + 1]);
            float ps0 = v0 * as0 + v1 * as1, pd0 = v0 * ad0 + v1 * ad1;
            float ps1 = v2 * as0 + v3 * as1, pd1 = v2 * ad0 + v3 * ad1;
            ps0 += __shfl_xor_sync(~0u, ps0, 1); ps0 += __shfl_xor_sync(~0u, ps0, 2);
            pd0 += __shfl_xor_sync(~0u, pd0, 1); pd0 += __shfl_xor_sync(~0u, pd0, 2);
            ps1 += __shfl_xor_sync(~0u, ps1, 1); ps1 += __shfl_xor_sync(~0u, ps1, 2);
            pd1 += __shfl_xor_sync(~0u, pd1, 1); pd1 += __shfl_xor_sync(~0u, pd1, 2);
            if (qp == 0) {
                int h = wn * 4 + nt;
                if (r0g < NN) { g_asrc1[r0g * H1 + h] = ps0; g_adst1[r0g * H1 + h] = pd0; }
                if (r1g < NN) { g_asrc1[r1g * H1 + h] = ps1; g_adst1[r1g * H1 + h] = pd1; }
            }
        }
    }
}

// ---------------- layer-1: fused softmax-agg + bias + ELU + GEMM2 + att projections ----------------
// warp per destination node; 4-wide unrolled gather loop (R14 structure).
__global__ __launch_bounds__(256) void k_agg1(const float* __restrict__ b1,
                                              const float* __restrict__ W2,
                                              const float* __restrict__ as2,
                                              const float* __restrict__ ad2) {
    __shared__ __align__(16) float sW[C2][F1];   // W2 transposed: sW[class][k]
    __shared__ float sas[C2], sad[C2];
    int tid = threadIdx.x;
    for (int idx = tid; idx < F1 * C2; idx += 256) {
        int k = idx / C2, j = idx % C2;
        sW[j][k] = W2[idx];
    }
    if (tid < C2) { sas[tid] = as2[tid]; sad[tid] = ad2[tid]; }
    __syncthreads();

    int n = blockIdx.x * 8 + (tid >> 5);
    if (n >= NN) return;
    int l = tid & 31;
    int h = l >> 1;
    int beg = g_row[n], end = g_row[n + 1];
    float ad = g_adst1[n * H1 + h];
    float ax = 0.f, ay = 0.f, az = 0.f, aw = 0.f, wsum = 0.f;

    int e = beg;
    for (; e + 4 <= end; e += 4) {
        int s0 = __ldg(&g_esrc[e + 0]);
        int s1 = __ldg(&g_esrc[e + 1]);
        int s2 = __ldg(&g_esrc[e + 2]);
        int s3 = __ldg(&g_esrc[e + 3]);
        float a0 = __ldg(&g_asrc1[s0 * H1 + h]);
        float a1 = __ldg(&g_asrc1[s1 * H1 + h]);
        float a2 = __ldg(&g_asrc1[s2 * H1 + h]);
        float a3 = __ldg(&g_asrc1[s3 * H1 + h]);
        uint2 u0 = *(const uint2*)&g_h1h[(size_t)s0 * F1 + l * 4];
        uint2 u1 = *(const uint2*)&g_h1h[(size_t)s1 * F1 + l * 4];
        uint2 u2 = *(const uint2*)&g_h1h[(size_t)s2 * F1 + l * 4];
        uint2 u3 = *(const uint2*)&g_h1h[(size_t)s3 * F1 + l * 4];
        float w0 = __expf(lrelu(a0 + ad));
        float w1 = __expf(lrelu(a1 + ad));
        float w2 = __expf(lrelu(a2 + ad));
        float w3 = __expf(lrelu(a3 + ad));
        float2 f0a = __half22float2(*(__half2*)&u0.x), f0b = __half22float2(*(__half2*)&u0.y);
        float2 f1a = __half22float2(*(__half2*)&u1.x), f1b = __half22float2(*(__half2*)&u1.y);
        float2 f2a = __half22float2(*(__half2*)&u2.x), f2b = __half22float2(*(__half2*)&u2.y);
        float2 f3a = __half22float2(*(__half2*)&u3.x), f3b = __half22float2(*(__half2*)&u3.y);
        ax += w0 * f0a.x + w1 * f1a.x + w2 * f2a.x + w3 * f3a.x;
        ay += w0 * f0a.y + w1 * f1a.y + w2 * f2a.y + w3 * f3a.y;
        az += w0 * f0b.x + w1 * f1b.x + w2 * f2b.x + w3 * f3b.x;
        aw += w0 * f0b.y + w1 * f1b.y + w2 * f2b.y + w3 * f3b.y;
        wsum += (w0 + w1) + (w2 + w3);
    }
    for (; e < end; e++) {
        int s = __ldg(&g_esrc[e]);
        float as = __ldg(&g_asrc1[s * H1 + h]);
        float w = __expf(lrelu(as + ad));
        uint2 u = *(const uint2*)&g_h1h[(size_t)s * F1 + l * 4];
        float2 fa = __half22float2(*(__half2*)&u.x), fb = __half22float2(*(__half2*)&u.y);
        ax += w * fa.x; ay += w * fa.y; az += w * fb.x; aw += w * fb.y;
        wsum += w;
    }

    float inv = __fdividef(1.f, wsum + 1e-16f);
    float4 bb = *(const float4*)&b1[l * 4];
    float o0 = ax * inv + bb.x, o1 = ay * inv + bb.y;
    float o2 = az * inv + bb.z, o3 = aw * inv + bb.w;
    o0 = o0 > 0.f ? o0 : expm1f(o0);
    o1 = o1 > 0.f ? o1 : expm1f(o1);
    o2 = o2 > 0.f ? o2 : expm1f(o2);
    o3 = o3 > 0.f ? o3 : expm1f(o3);

    // ---- fused GEMM2: h2[n] = out1[n] @ W2 ----
    float mine = 0.f;
#pragma unroll
    for (int j = 0; j < C2; j++) {
        float4 w = *(const float4*)&sW[j][l * 4];
        float p = o0 * w.x + o1 * w.y + o2 * w.z + o3 * w.w;
#pragma unroll
        for (int o = 16; o; o >>= 1) p += __shfl_xor_sync(0xffffffffu, p, o);
        if (l == j) mine = p;
    }
    if (l < C2P) g_h2h[n * C2P + l] = __float2half_rn((l < C2) ? mine : 0.f);

    float psrc = (l < C2) ? mine * sas[l] : 0.f;
    float pdst = (l < C2) ? mine * sad[l] : 0.f;
#pragma unroll
    for (int o = 16; o; o >>= 1) {
        psrc += __shfl_xor_sync(0xffffffffu, psrc, o);
        pdst += __shfl_xor_sync(0xffffffffu, pdst, o);
    }
    if (l == 0) { g_asrc2[n] = psrc; g_adst2[n] = pdst; }
}

// ---------------- layer-2: fused softmax-agg + normalize + bias + log_softmax ----------------
// warp per destination node; lane l = class; 4-wide unrolled gather loop.
__global__ __launch_bounds__(256) void k_agg2(const float* __restrict__ b2,
                                              float* __restrict__ out) {
    int n = blockIdx.x * 8 + (threadIdx.x >> 5);
    if (n >= NN) return;
    int l = threadIdx.x & 31;
    int beg = g_row[n], end = g_row[n + 1];
    float ad = g_adst2[n];
    float acc = 0.f, wsum = 0.f;
    int lc = (l < C2) ? l : 0;

    int e = beg;
    for (; e + 4 <= end; e += 4) {
        int s0 = __ldg(&g_esrc[e + 0]);
        int s1 = __ldg(&g_esrc[e + 1]);
        int s2 = __ldg(&g_esrc[e + 2]);
        int s3 = __ldg(&g_esrc[e + 3]);
        float a0 = __ldg(&g_asrc2[s0]);
        float a1 = __ldg(&g_asrc2[s1]);
        float a2 = __ldg(&g_asrc2[s2]);
        float a3 = __ldg(&g_asrc2[s3]);
        float v0 = __half2float(g_h2h[s0 * C2P + lc]);
        float v1 = __half2float(g_h2h[s1 * C2P + lc]);
        float v2 = __half2float(g_h2h[s2 * C2P + lc]);
        float v3 = __half2float(g_h2h[s3 * C2P + lc]);
        float w0 = __expf(lrelu(a0 + ad));
        float w1 = __expf(lrelu(a1 + ad));
        float w2 = __expf(lrelu(a2 + ad));
        float w3 = __expf(lrelu(a3 + ad));
        acc += w0 * v0 + w1 * v1 + w2 * v2 + w3 * v3;
        wsum += (w0 + w1) + (w2 + w3);
    }
    for (; e < end; e++) {
        int s = __ldg(&g_esrc[e]);
        float as = __ldg(&g_asrc2[s]);
        float w = __expf(lrelu(as + ad));
        acc += w * __half2float(g_h2h[s * C2P + lc]);
        wsum += w;
    }

    float val = __fdividef(acc, wsum + 1e-16f) + ((l < C2) ? b2[l] : 0.f);
    float z = (l < C2) ? val : -1e30f;
    float m = z;
#pragma unroll
    for (int o = 16; o; o >>= 1) m = fmaxf(m, __shfl_xor_sync(0xffffffffu, m, o));
    float ex = (l < C2) ? expf(z - m) : 0.f;
    float ssum = ex;
#pragma unroll
    for (int o = 16; o; o >>= 1) ssum += __shfl_xor_sync(0xffffffffu, ssum, o);
    float lse = m + logf(ssum);
    if (l < C2) out[n * C2 + l] = z - lse;
}

// ---------------- launch ----------------
extern "C" void kernel_launch(void* const* d_in, const int* in_sizes, int n_in,
                              void* d_out, int out_size) {
    const float* x   = (const float*)d_in[0];
    const int*   ei  = (const int*)  d_in[1];
    const float* W1  = (const float*)d_in[2];
    const float* as1 = (const float*)d_in[3];
    const float* ad1 = (const float*)d_in[4];
    const float* b1  = (const float*)d_in[5];
    const float* W2  = (const float*)d_in[6];
    const float* as2 = (const float*)d_in[7];
    const float* ad2 = (const float*)d_in[8];
    const float* b2  = (const float*)d_in[9];
    float* out = (float*)d_out;

    static int inited = 0;
    static cudaStream_t s2;
    static cudaEvent_t evFork, evPrep, evJoin;
    if (!inited) {
        cudaFuncSetAttribute(k_gemm1, cudaFuncAttributeMaxDynamicSharedMemorySize, G1_SMEM);
        cudaStreamCreateWithFlags(&s2, cudaStreamNonBlocking);
        cudaEventCreateWithFlags(&evFork, cudaEventDisableTiming);
        cudaEventCreateWithFlags(&evPrep, cudaEventDisableTiming);
        cudaEventCreateWithFlags(&evJoin, cudaEventDisableTiming);
        inited = 1;
    }

    // fork: prepB + CSR chain run on s2, overlapped with gemm1 on the main stream
    cudaEventRecord(evFork, 0);
    cudaStreamWaitEvent(s2, evFork, 0);

    k_prepB<<<(FIN * F1 + 255) / 256, 256, 0, s2>>>(W1);
    cudaEventRecord(evPrep, s2);
    k_init<<<NB1, 256, 0, s2>>>();
    k_hist<<<(ENL + 255) / 256, 256, 0, s2>>>(ei);
    k_scan1<<<NB1, 256, 0, s2>>>();
    k_scan2<<<1, 512, 0, s2>>>();
    k_scan3<<<NB1, 256, 0, s2>>>();
    k_scatter<<<(ENL + 255) / 256, 256, 0, s2>>>(ei);
    cudaEventRecord(evJoin, s2);

    cudaStreamWaitEvent(0, evPrep, 0);
    k_gemm1<<<(NN + 127) / 128, 512, G1_SMEM>>>(x, as1, ad1);

    // join: agg1 needs both the CSR and gemm1 results
    cudaStreamWaitEvent(0, evJoin, 0);
    k_agg1<<<(NN + 7) / 8, 256>>>(b1, W2, as2, ad2);
    k_agg2<<<(NN + 7) / 8, 256>>>(b2, out);
}